// round 5
// baseline (speedup 1.0000x reference)
#include <cuda_runtime.h>
#include <cstdint>

#define N_NODES 50000
#define NNZ_C   800000
#define N_ADJ   6
#define K_DIM   256
#define H_DIM   128
#define LN_EPS  1e-5f

// ---------------------------------------------------------------------------
// Device-global scratch
// ---------------------------------------------------------------------------
__device__ float g_h[(size_t)N_NODES * H_DIM];              // s0 = x@W+b
__device__ float g_state[3][(size_t)N_NODES * H_DIM];       // s1, s2, s3
__device__ int   g_wcur[N_ADJ][N_NODES];                    // counts -> cursors
__device__ int   g_rowptr[N_ADJ][N_NODES + 1];              // CSR row pointers
__device__ int2  g_edges[N_ADJ][NNZ_C];                     // packed (col, val)

__device__ __forceinline__ float* state_ptr(int id) {
    return (id == 0) ? g_h : g_state[id - 1];
}

// ---------------------------------------------------------------------------
// CSR build: zero counters -> histogram -> scan -> scatter
// Flat grids (one thread per element) so atomic latency is hidden by
// occupancy instead of serialized inside grid-stride loops.
// ---------------------------------------------------------------------------
__global__ void zero_cnt_kernel() {
    const int i = blockIdx.x * blockDim.x + threadIdx.x;
    if (i < N_ADJ * N_NODES) (&g_wcur[0][0])[i] = 0;
}

// grid: (NNZ_C/256, N_ADJ)
__global__ __launch_bounds__(256) void hist_kernel(const int* __restrict__ rows_base) {
    const int e = blockIdx.x * blockDim.x + threadIdx.x;
    const int* rows = rows_base + (size_t)blockIdx.y * NNZ_C;
    if (e < NNZ_C) {
        const int row = __ldg(rows + e);
        atomicAdd(&g_wcur[blockIdx.y][row], 1);
    }
}

// One block per adjacency: 256 threads, contiguous row chunks + block scan.
__global__ __launch_bounds__(256) void scan_kernel() {
    const int a = blockIdx.x;
    const int t = threadIdx.x;
    const int CHUNK = (N_NODES + 255) / 256;
    const int start = t * CHUNK;
    const int end = min(start + CHUNK, N_NODES);

    int sum = 0;
    for (int r = start; r < end; r++) sum += g_wcur[a][r];

    __shared__ int sh[256];
    sh[t] = sum;
    __syncthreads();
    for (int off = 1; off < 256; off <<= 1) {
        int v = (t >= off) ? sh[t - off] : 0;
        __syncthreads();
        sh[t] += v;
        __syncthreads();
    }
    int run = sh[t] - sum;
    for (int r = start; r < end; r++) {
        const int c = g_wcur[a][r];
        g_rowptr[a][r] = run;
        g_wcur[a][r] = run;          // becomes scatter cursor
        run += c;
    }
    if (t == 255) g_rowptr[a][N_NODES] = run;
}

// grid: (NNZ_C/256, N_ADJ)
__global__ __launch_bounds__(256) void scatter_kernel(const int*   __restrict__ rows_base,
                                                      const int*   __restrict__ cols_base,
                                                      const float* __restrict__ vals_base) {
    const int a = blockIdx.y;
    const int e = blockIdx.x * blockDim.x + threadIdx.x;
    const size_t base = (size_t)a * NNZ_C;
    if (e < NNZ_C) {
        const int   row = __ldg(rows_base + base + e);
        const int   col = __ldg(cols_base + base + e);
        const float v   = __ldg(vals_base + base + e);
        const int pos = atomicAdd(&g_wcur[a][row], 1);
        g_edges[a][pos] = make_int2(col, __float_as_int(v));
    }
}

// ---------------------------------------------------------------------------
// GEMM: g_h = X[50000,256] @ W[256,128] + b   (128x128 tile, 8x8/thread)
// ---------------------------------------------------------------------------
__global__ __launch_bounds__(256) void gemm_kernel(const float* __restrict__ X,
                                                   const float* __restrict__ W,
                                                   const float* __restrict__ bias) {
    __shared__ float As[8][128];
    __shared__ float Bs[8][128];

    const int tid = threadIdx.x;
    const int tx = tid & 15;
    const int ty = tid >> 4;
    const int row0 = blockIdx.x * 128;

    const int arow = tid >> 1;
    const int ak   = (tid & 1) * 4;
    const int grow = min(row0 + arow, N_NODES - 1);
    const int brow = tid >> 5;
    const int bcol = (tid & 31) * 4;

    float acc[8][8];
#pragma unroll
    for (int i = 0; i < 8; i++)
#pragma unroll
        for (int j = 0; j < 8; j++) acc[i][j] = 0.f;

    for (int k0 = 0; k0 < K_DIM; k0 += 8) {
        const float4 av = *reinterpret_cast<const float4*>(
            X + (size_t)grow * K_DIM + k0 + ak);
        const float4 bv = *reinterpret_cast<const float4*>(
            W + (size_t)(k0 + brow) * H_DIM + bcol);
        __syncthreads();
        As[ak + 0][arow] = av.x;
        As[ak + 1][arow] = av.y;
        As[ak + 2][arow] = av.z;
        As[ak + 3][arow] = av.w;
        *reinterpret_cast<float4*>(&Bs[brow][bcol]) = bv;
        __syncthreads();

#pragma unroll
        for (int kk = 0; kk < 8; kk++) {
            float a[8], b[8];
            const float4 a0 = *reinterpret_cast<const float4*>(&As[kk][ty * 8]);
            const float4 a1 = *reinterpret_cast<const float4*>(&As[kk][ty * 8 + 4]);
            const float4 b0 = *reinterpret_cast<const float4*>(&Bs[kk][tx * 8]);
            const float4 b1 = *reinterpret_cast<const float4*>(&Bs[kk][tx * 8 + 4]);
            a[0]=a0.x; a[1]=a0.y; a[2]=a0.z; a[3]=a0.w;
            a[4]=a1.x; a[5]=a1.y; a[6]=a1.z; a[7]=a1.w;
            b[0]=b0.x; b[1]=b0.y; b[2]=b0.z; b[3]=b0.w;
            b[4]=b1.x; b[5]=b1.y; b[6]=b1.z; b[7]=b1.w;
#pragma unroll
            for (int i = 0; i < 8; i++)
#pragma unroll
                for (int j = 0; j < 8; j++) acc[i][j] += a[i] * b[j];
        }
    }

    const int colb = tx * 8;
    const float4 bia0 = *reinterpret_cast<const float4*>(bias + colb);
    const float4 bia1 = *reinterpret_cast<const float4*>(bias + colb + 4);
#pragma unroll
    for (int i = 0; i < 8; i++) {
        const int row = row0 + ty * 8 + i;
        if (row < N_NODES) {
            float4 o0, o1;
            o0.x = acc[i][0] + bia0.x; o0.y = acc[i][1] + bia0.y;
            o0.z = acc[i][2] + bia0.z; o0.w = acc[i][3] + bia0.w;
            o1.x = acc[i][4] + bia1.x; o1.y = acc[i][5] + bia1.y;
            o1.z = acc[i][6] + bia1.z; o1.w = acc[i][7] + bia1.w;
            float* op = g_h + (size_t)row * H_DIM + colb;
            *reinterpret_cast<float4*>(op)     = o0;
            *reinterpret_cast<float4*>(op + 4) = o1;
        }
    }
}

// ---------------------------------------------------------------------------
// CSR SpMM, single term: one warp per row, 4-way software-pipelined gathers.
// accum=0: dst = sum; accum=1: dst += sum (safe across kernel boundaries,
// each row owned by exactly one warp -> no atomics anywhere).
// ---------------------------------------------------------------------------
__global__ __launch_bounds__(256) void spmm_row_kernel(const int* __restrict__ idxp,
                                                       int src_id, int dst_id,
                                                       int accum) {
    const int lane = threadIdx.x & 31;
    const int row  = (blockIdx.x * blockDim.x + threadIdx.x) >> 5;
    if (row >= N_NODES) return;

    const int a = __ldg(idxp);
    const float* __restrict__ src = state_ptr(src_id);
    float*       __restrict__ dst = state_ptr(dst_id);
    const int2*  __restrict__ el  = g_edges[a];

    int e         = __ldg(&g_rowptr[a][row]);
    const int end = __ldg(&g_rowptr[a][row + 1]);

    float4 acc0 = make_float4(0.f, 0.f, 0.f, 0.f);
    float4 acc1 = make_float4(0.f, 0.f, 0.f, 0.f);

    // 4-way unrolled: 4 independent gathers in flight per iteration
    for (; e + 4 <= end; e += 4) {
        const int2 c0 = __ldg(el + e);
        const int2 c1 = __ldg(el + e + 1);
        const int2 c2 = __ldg(el + e + 2);
        const int2 c3 = __ldg(el + e + 3);
        const float4 x0 = __ldg(reinterpret_cast<const float4*>(
                                    src + (size_t)c0.x * H_DIM) + lane);
        const float4 x1 = __ldg(reinterpret_cast<const float4*>(
                                    src + (size_t)c1.x * H_DIM) + lane);
        const float4 x2 = __ldg(reinterpret_cast<const float4*>(
                                    src + (size_t)c2.x * H_DIM) + lane);
        const float4 x3 = __ldg(reinterpret_cast<const float4*>(
                                    src + (size_t)c3.x * H_DIM) + lane);
        const float v0 = __int_as_float(c0.y);
        const float v1 = __int_as_float(c1.y);
        const float v2 = __int_as_float(c2.y);
        const float v3 = __int_as_float(c3.y);
        acc0.x += v0 * x0.x; acc0.y += v0 * x0.y; acc0.z += v0 * x0.z; acc0.w += v0 * x0.w;
        acc1.x += v1 * x1.x; acc1.y += v1 * x1.y; acc1.z += v1 * x1.z; acc1.w += v1 * x1.w;
        acc0.x += v2 * x2.x; acc0.y += v2 * x2.y; acc0.z += v2 * x2.z; acc0.w += v2 * x2.w;
        acc1.x += v3 * x3.x; acc1.y += v3 * x3.y; acc1.z += v3 * x3.z; acc1.w += v3 * x3.w;
    }
    for (; e < end; e++) {
        const int2 cv = __ldg(el + e);
        const float v = __int_as_float(cv.y);
        const float4 xv = __ldg(reinterpret_cast<const float4*>(
                                    src + (size_t)cv.x * H_DIM) + lane);
        acc0.x += v * xv.x; acc0.y += v * xv.y; acc0.z += v * xv.z; acc0.w += v * xv.w;
    }

    acc0.x += acc1.x; acc0.y += acc1.y; acc0.z += acc1.z; acc0.w += acc1.w;

    float4* dp = reinterpret_cast<float4*>(dst + (size_t)row * H_DIM) + lane;
    if (accum) {
        const float4 d = *dp;
        acc0.x += d.x; acc0.y += d.y; acc0.z += d.z; acc0.w += d.w;
    }
    *dp = acc0;
}

// ---------------------------------------------------------------------------
// LayerNorm + exact-erf GELU, one warp per row
// ---------------------------------------------------------------------------
__global__ __launch_bounds__(256) void ln_gelu_kernel(const float* __restrict__ gamma,
                                                      const float* __restrict__ beta,
                                                      float* __restrict__ out) {
    const int warp = (blockIdx.x * blockDim.x + threadIdx.x) >> 5;
    const int lane = threadIdx.x & 31;
    if (warp >= N_NODES) return;

    const float* yrow = g_state[2] + (size_t)warp * H_DIM;
    const float4 v = *reinterpret_cast<const float4*>(yrow + lane * 4);

    float s  = v.x + v.y + v.z + v.w;
    float sq = v.x * v.x + v.y * v.y + v.z * v.z + v.w * v.w;
#pragma unroll
    for (int o = 16; o; o >>= 1) {
        s  += __shfl_xor_sync(0xFFFFFFFFu, s,  o);
        sq += __shfl_xor_sync(0xFFFFFFFFu, sq, o);
    }
    const float mean = s * (1.f / H_DIM);
    const float var  = sq * (1.f / H_DIM) - mean * mean;
    const float rstd = rsqrtf(var + LN_EPS);

    const float4 g = *reinterpret_cast<const float4*>(gamma + lane * 4);
    const float4 b = *reinterpret_cast<const float4*>(beta  + lane * 4);

    auto gelu = [](float t) {
        return 0.5f * t * (1.f + erff(t * 0.7071067811865476f));
    };
    float4 r;
    r.x = gelu((v.x - mean) * rstd * g.x + b.x);
    r.y = gelu((v.y - mean) * rstd * g.y + b.y);
    r.z = gelu((v.z - mean) * rstd * g.z + b.z);
    r.w = gelu((v.w - mean) * rstd * g.w + b.w);

    *reinterpret_cast<float4*>(out + (size_t)warp * H_DIM + lane * 4) = r;
}

// ---------------------------------------------------------------------------
// kernel_launch
// inputs: x, adj_rows, adj_cols, adj_vals, idxes_seq, idxes_res,
//         W, b, gamma, beta
// ---------------------------------------------------------------------------
extern "C" void kernel_launch(void* const* d_in, const int* in_sizes, int n_in,
                              void* d_out, int out_size) {
    const float* x        = (const float*)d_in[0];
    const int*   adj_rows = (const int*)  d_in[1];
    const int*   adj_cols = (const int*)  d_in[2];
    const float* adj_vals = (const float*)d_in[3];
    const int*   idx_seq  = (const int*)  d_in[4];
    const int*   idx_res  = (const int*)  d_in[5];
    const float* W        = (const float*)d_in[6];
    const float* b        = (const float*)d_in[7];
    const float* gamma    = (const float*)d_in[8];
    const float* beta     = (const float*)d_in[9];
    float*       out      = (float*)d_out;

    // ---- CSR build ----
    dim3 egrid((NNZ_C + 255) / 256, N_ADJ);
    zero_cnt_kernel<<<(N_ADJ * N_NODES + 255) / 256, 256>>>();
    hist_kernel<<<egrid, 256>>>(adj_rows);
    scan_kernel<<<N_ADJ, 256>>>();
    scatter_kernel<<<egrid, 256>>>(adj_rows, adj_cols, adj_vals);

    // ---- affine ----
    gemm_kernel<<<(N_NODES + 127) / 128, 256>>>(x, W, b);

    // ---- propagation (state ids: 0=s0, 1=s1, 2=s2, 3=s3) ----
    const int RGRID = (N_NODES * 32 + 255) / 256;
    // s1 = A[seq0] @ s0
    spmm_row_kernel<<<RGRID, 256>>>(idx_seq + 0, 0, 1, 0);
    // s2 = A[seq1] @ s1 + A[res0] @ s0
    spmm_row_kernel<<<RGRID, 256>>>(idx_seq + 1, 1, 2, 0);
    spmm_row_kernel<<<RGRID, 256>>>(idx_res + 0, 0, 2, 1);
    // s3 = A[seq2] @ s2 + A[res1] @ s0 + A[res2] @ s1
    spmm_row_kernel<<<RGRID, 256>>>(idx_seq + 2, 2, 3, 0);
    spmm_row_kernel<<<RGRID, 256>>>(idx_res + 1, 0, 3, 1);
    spmm_row_kernel<<<RGRID, 256>>>(idx_res + 2, 1, 3, 1);

    // ---- LN + GELU ----
    ln_gelu_kernel<<<RGRID, 256>>>(gamma, beta, out);
}

// round 6
// speedup vs baseline: 1.3158x; 1.3158x over previous
#include <cuda_runtime.h>
#include <cstdint>

#define N_NODES 50000
#define NNZ_C   800000
#define N_ADJ   6
#define K_DIM   256
#define H_DIM   128
#define LN_EPS  1e-5f

// ---------------------------------------------------------------------------
// Device-global scratch
// ---------------------------------------------------------------------------
__device__ float g_h[(size_t)N_NODES * H_DIM];            // s0 = x@W+b
__device__ float g_acc[3][(size_t)N_NODES * H_DIM];       // s1, s2, s3 (RED targets)
__device__ int2  g_ecv[N_ADJ][NNZ_C];                     // zipped (col, val bits)

__device__ __forceinline__ float* state_ptr(int id) {
    return (id == 0) ? g_h : g_acc[id - 1];
}

// ---------------------------------------------------------------------------
// Zero the accumulators (RED targets) each call
// ---------------------------------------------------------------------------
__global__ void zero_kernel() {
    const size_t n4 = (size_t)3 * N_NODES * H_DIM / 4;
    float4* p = reinterpret_cast<float4*>(&g_acc[0][0]);
    const float4 z = make_float4(0.f, 0.f, 0.f, 0.f);
    for (size_t i = (size_t)blockIdx.x * blockDim.x + threadIdx.x; i < n4;
         i += (size_t)gridDim.x * blockDim.x)
        p[i] = z;
}

// ---------------------------------------------------------------------------
// Zip cols+vals into int2 (streaming, no reordering). grid: flat over all.
// ---------------------------------------------------------------------------
__global__ __launch_bounds__(256) void zip_kernel(const int*   __restrict__ cols_base,
                                                  const float* __restrict__ vals_base) {
    const size_t i = (size_t)blockIdx.x * blockDim.x + threadIdx.x;
    if (i < (size_t)N_ADJ * NNZ_C)
        (&g_ecv[0][0])[i] = make_int2(__ldg(cols_base + i),
                                      __float_as_int(__ldg(vals_base + i)));
}

// ---------------------------------------------------------------------------
// GEMM: g_h = X[50000,256] @ W[256,128] + b   (128x128 tile, 8x8/thread)
// ---------------------------------------------------------------------------
__global__ __launch_bounds__(256) void gemm_kernel(const float* __restrict__ X,
                                                   const float* __restrict__ W,
                                                   const float* __restrict__ bias) {
    __shared__ float As[8][128];
    __shared__ float Bs[8][128];

    const int tid = threadIdx.x;
    const int tx = tid & 15;
    const int ty = tid >> 4;
    const int row0 = blockIdx.x * 128;

    const int arow = tid >> 1;
    const int ak   = (tid & 1) * 4;
    const int grow = min(row0 + arow, N_NODES - 1);
    const int brow = tid >> 5;
    const int bcol = (tid & 31) * 4;

    float acc[8][8];
#pragma unroll
    for (int i = 0; i < 8; i++)
#pragma unroll
        for (int j = 0; j < 8; j++) acc[i][j] = 0.f;

    for (int k0 = 0; k0 < K_DIM; k0 += 8) {
        const float4 av = *reinterpret_cast<const float4*>(
            X + (size_t)grow * K_DIM + k0 + ak);
        const float4 bv = *reinterpret_cast<const float4*>(
            W + (size_t)(k0 + brow) * H_DIM + bcol);
        __syncthreads();
        As[ak + 0][arow] = av.x;
        As[ak + 1][arow] = av.y;
        As[ak + 2][arow] = av.z;
        As[ak + 3][arow] = av.w;
        *reinterpret_cast<float4*>(&Bs[brow][bcol]) = bv;
        __syncthreads();

#pragma unroll
        for (int kk = 0; kk < 8; kk++) {
            float a[8], b[8];
            const float4 a0 = *reinterpret_cast<const float4*>(&As[kk][ty * 8]);
            const float4 a1 = *reinterpret_cast<const float4*>(&As[kk][ty * 8 + 4]);
            const float4 b0 = *reinterpret_cast<const float4*>(&Bs[kk][tx * 8]);
            const float4 b1 = *reinterpret_cast<const float4*>(&Bs[kk][tx * 8 + 4]);
            a[0]=a0.x; a[1]=a0.y; a[2]=a0.z; a[3]=a0.w;
            a[4]=a1.x; a[5]=a1.y; a[6]=a1.z; a[7]=a1.w;
            b[0]=b0.x; b[1]=b0.y; b[2]=b0.z; b[3]=b0.w;
            b[4]=b1.x; b[5]=b1.y; b[6]=b1.z; b[7]=b1.w;
#pragma unroll
            for (int i = 0; i < 8; i++)
#pragma unroll
                for (int j = 0; j < 8; j++) acc[i][j] += a[i] * b[j];
        }
    }

    const int colb = tx * 8;
    const float4 bia0 = *reinterpret_cast<const float4*>(bias + colb);
    const float4 bia1 = *reinterpret_cast<const float4*>(bias + colb + 4);
#pragma unroll
    for (int i = 0; i < 8; i++) {
        const int row = row0 + ty * 8 + i;
        if (row < N_NODES) {
            float4 o0, o1;
            o0.x = acc[i][0] + bia0.x; o0.y = acc[i][1] + bia0.y;
            o0.z = acc[i][2] + bia0.z; o0.w = acc[i][3] + bia0.w;
            o1.x = acc[i][4] + bia1.x; o1.y = acc[i][5] + bia1.y;
            o1.z = acc[i][6] + bia1.z; o1.w = acc[i][7] + bia1.w;
            float* op = g_h + (size_t)row * H_DIM + colb;
            *reinterpret_cast<float4*>(op)     = o0;
            *reinterpret_cast<float4*>(op + 4) = o1;
        }
    }
}

// ---------------------------------------------------------------------------
// SpMM (COO + RED): one warp per 32-edge chunk. Lane-cooperative metadata
// (1x LDG.32 for rows + 1x LDG.64 for (col,val) per 32 edges), shfl
// broadcast, then 32 independent gather+RED pairs (deep MLP, no writeback).
// grid: NNZ_C/32 warps, flat.
// ---------------------------------------------------------------------------
__global__ __launch_bounds__(256) void spmm_kernel(const int* __restrict__ rows_base,
                                                   const int* __restrict__ idxp,
                                                   int src_id, int dst_id) {
    const int lane  = threadIdx.x & 31;
    const int chunk = (blockIdx.x * blockDim.x + threadIdx.x) >> 5;
    if (chunk >= NNZ_C / 32) return;

    const int a = __ldg(idxp);
    const float* __restrict__ src = state_ptr(src_id);
    float*       __restrict__ dst = state_ptr(dst_id);

    const size_t e0 = (size_t)chunk * 32;
    const int  myrow = __ldg(rows_base + (size_t)a * NNZ_C + e0 + lane);
    const int2 mycv  = __ldg(&g_ecv[a][e0 + lane]);

#pragma unroll
    for (int j = 0; j < 32; j++) {
        const int   row = __shfl_sync(0xFFFFFFFFu, myrow, j);
        const int   col = __shfl_sync(0xFFFFFFFFu, mycv.x, j);
        const float val = __int_as_float(__shfl_sync(0xFFFFFFFFu, mycv.y, j));
        const float4 xv = __ldg(reinterpret_cast<const float4*>(
                                    src + (size_t)col * H_DIM) + lane);
        float* p = dst + (size_t)row * H_DIM + lane * 4;
        asm volatile("red.global.add.v4.f32 [%0], {%1, %2, %3, %4};"
                     :: "l"(p), "f"(xv.x * val), "f"(xv.y * val),
                        "f"(xv.z * val), "f"(xv.w * val)
                     : "memory");
    }
}

// ---------------------------------------------------------------------------
// LayerNorm + exact-erf GELU, one warp per row
// ---------------------------------------------------------------------------
__global__ __launch_bounds__(256) void ln_gelu_kernel(const float* __restrict__ gamma,
                                                      const float* __restrict__ beta,
                                                      float* __restrict__ out) {
    const int warp = (blockIdx.x * blockDim.x + threadIdx.x) >> 5;
    const int lane = threadIdx.x & 31;
    if (warp >= N_NODES) return;

    const float* yrow = g_acc[2] + (size_t)warp * H_DIM;
    const float4 v = *reinterpret_cast<const float4*>(yrow + lane * 4);

    float s  = v.x + v.y + v.z + v.w;
    float sq = v.x * v.x + v.y * v.y + v.z * v.z + v.w * v.w;
#pragma unroll
    for (int o = 16; o; o >>= 1) {
        s  += __shfl_xor_sync(0xFFFFFFFFu, s,  o);
        sq += __shfl_xor_sync(0xFFFFFFFFu, sq, o);
    }
    const float mean = s * (1.f / H_DIM);
    const float var  = sq * (1.f / H_DIM) - mean * mean;
    const float rstd = rsqrtf(var + LN_EPS);

    const float4 g = *reinterpret_cast<const float4*>(gamma + lane * 4);
    const float4 b = *reinterpret_cast<const float4*>(beta  + lane * 4);

    auto gelu = [](float t) {
        return 0.5f * t * (1.f + erff(t * 0.7071067811865476f));
    };
    float4 r;
    r.x = gelu((v.x - mean) * rstd * g.x + b.x);
    r.y = gelu((v.y - mean) * rstd * g.y + b.y);
    r.z = gelu((v.z - mean) * rstd * g.z + b.z);
    r.w = gelu((v.w - mean) * rstd * g.w + b.w);

    *reinterpret_cast<float4*>(out + (size_t)warp * H_DIM + lane * 4) = r;
}

// ---------------------------------------------------------------------------
// kernel_launch
// inputs: x, adj_rows, adj_cols, adj_vals, idxes_seq, idxes_res,
//         W, b, gamma, beta
// ---------------------------------------------------------------------------
extern "C" void kernel_launch(void* const* d_in, const int* in_sizes, int n_in,
                              void* d_out, int out_size) {
    const float* x        = (const float*)d_in[0];
    const int*   adj_rows = (const int*)  d_in[1];
    const int*   adj_cols = (const int*)  d_in[2];
    const float* adj_vals = (const float*)d_in[3];
    const int*   idx_seq  = (const int*)  d_in[4];
    const int*   idx_res  = (const int*)  d_in[5];
    const float* W        = (const float*)d_in[6];
    const float* b        = (const float*)d_in[7];
    const float* gamma    = (const float*)d_in[8];
    const float* beta     = (const float*)d_in[9];
    float*       out      = (float*)d_out;

    zero_kernel<<<1024, 256>>>();
    zip_kernel<<<(N_ADJ * NNZ_C + 255) / 256, 256>>>(adj_cols, adj_vals);
    gemm_kernel<<<(N_NODES + 127) / 128, 256>>>(x, W, b);

    const int SPMM_GRID = (NNZ_C / 32 * 32 + 255) / 256;   // 25000 warps
    // state ids: 0 = s0 (g_h), 1 = s1, 2 = s2, 3 = s3
    // s1 = A[seq0] @ s0
    spmm_kernel<<<SPMM_GRID, 256>>>(adj_rows, idx_seq + 0, 0, 1);
    // s2 = A[seq1] @ s1 + A[res0] @ s0
    spmm_kernel<<<SPMM_GRID, 256>>>(adj_rows, idx_seq + 1, 1, 2);
    spmm_kernel<<<SPMM_GRID, 256>>>(adj_rows, idx_res + 0, 0, 2);
    // s3 = A[seq2] @ s2 + A[res1] @ s0 + A[res2] @ s1
    spmm_kernel<<<SPMM_GRID, 256>>>(adj_rows, idx_seq + 2, 2, 3);
    spmm_kernel<<<SPMM_GRID, 256>>>(adj_rows, idx_res + 1, 0, 3);
    spmm_kernel<<<SPMM_GRID, 256>>>(adj_rows, idx_res + 2, 1, 3);

    ln_gelu_kernel<<<(N_NODES * 32 + 255) / 256, 256>>>(gamma, beta, out);
}